// round 4
// baseline (speedup 1.0000x reference)
#include <cuda_runtime.h>

// Problem constants
#define NN 512
#define CC 64
#define RR 32
#define BT 32
#define NT 128

// channel swizzle: spreads the two 32-wide halves so 8 distinct float4s
// per warp-load cover all 32 banks (row stride 68)
#define SW(f) ((f) + (((f) >> 5) << 2))

// Shared memory layout (floats)
#define OFF_W1   0        // [32][68]    = 2176 (swizzled f)
#define OFF_W2   2176     // [64][68]    = 4352 (swizzled f; reused as partials)
#define OFF_B1   6528     // [64]
#define OFF_B2   6592     // [64]
#define OFF_RBF  6656     // [32][36]    = 1152
#define OFF_H    7808     // [32][68]    = 2176 (swizzled c)
#define OFF_X0   9984     // [32][68]    = 2176 (swizzled f)
#define OFF_X1   12160    // [3][32][68] = 6528 (swizzled f)
#define OFF_U    18688    // [32][4]     = 128
#define SMEM_FLOATS 18816
#define SMEM_BYTES (SMEM_FLOATS * 4)

extern __shared__ float smem[];

__global__ __launch_bounds__(NT, 3)
void conv_tfn_m_kernel(const float* __restrict__ gx0,
                       const float* __restrict__ gx1,
                       const float* __restrict__ grbf,
                       const float* __restrict__ gu,
                       const float* __restrict__ gw1,
                       const float* __restrict__ gb1,
                       const float* __restrict__ gw2,
                       const float* __restrict__ gb2,
                       float* __restrict__ out)
{
    const int a   = blockIdx.x;
    const int m   = blockIdx.y;     // which of the 5 radial MLPs / CG paths
    const int tid = threadIdx.x;

    float* sW1  = smem + OFF_W1;
    float* sW2  = smem + OFF_W2;
    float* sB1  = smem + OFF_B1;
    float* sB2  = smem + OFF_B2;
    float* sRBF = smem + OFF_RBF;
    float* sH   = smem + OFF_H;
    float* sX0  = smem + OFF_X0;
    float* sX1  = smem + OFF_X1;
    float* sU   = smem + OFF_U;

    // ---- load this MLP's weights (swizzled) ----
    {
        const float* p = gw1 + (size_t)m * RR * CC;
        for (int i = tid; i < RR * CC; i += NT) {
            int r = i >> 6, f = i & 63;
            sW1[r * 68 + SW(f)] = p[i];
        }
    }
    {
        const float* p = gw2 + (size_t)m * CC * CC;
        for (int i = tid; i < CC * CC; i += NT) {
            int c = i >> 6, f = i & 63;
            sW2[c * 68 + SW(f)] = p[i];
        }
    }
    if (tid < CC) {
        sB1[tid] = gb1[m * CC + tid];
        sB2[tid] = gb2[m * CC + tid];
    }

    // thread tile: 2 b's x 8 f's
    const int fb  = tid & 7;
    const int f0  = fb * 8;
    const int f0s = SW(f0);         // f0 multiple of 8 -> f0..f0+7 swizzle-contiguous by halves
    const int bb  = tid >> 3;
    const int b0  = bb * 2;

    // persistent output accumulators: [k(f within tile)][component 0..2]
    float acc[8][3];
    #pragma unroll
    for (int k = 0; k < 8; k++) { acc[k][0] = 0.f; acc[k][1] = 0.f; acc[k][2] = 0.f; }

    for (int bt = 0; bt < NN; bt += BT) {
        __syncthreads();   // previous tile's readers done

        // ---- stage tiles ----
        {
            const float* p = grbf + (size_t)a * NN * RR + (size_t)bt * RR;
            for (int i = tid; i < BT * RR; i += NT)
                sRBF[(i >> 5) * 36 + (i & 31)] = p[i];
        }
        {
            const float* p = gx0 + (size_t)bt * CC;
            for (int i = tid; i < BT * CC; i += NT) {
                int b = i >> 6, f = i & 63;
                sX0[b * 68 + SW(f)] = p[i];
            }
        }
        {
            const float* p = gx1 + (size_t)bt * CC * 3;
            for (int i = tid; i < BT * CC * 3; i += NT) {
                int b   = i / 192;
                int rem = i - b * 192;
                int f   = rem / 3;
                int c   = rem - f * 3;
                sX1[c * 2176 + b * 68 + SW(f)] = p[i];
            }
        }
        if (tid < BT * 3) {
            const float* p = gu + (size_t)a * NN * 3 + (size_t)bt * 3;
            int b = tid / 3, c = tid - b * 3;
            sU[b * 4 + c] = p[tid];
        }
        __syncthreads();

        // ---- GEMM1: H[b][f] = relu(rbf[b,:] @ W1 + b1) ----
        {
            float h0[8], h1[8];
            #pragma unroll
            for (int k = 0; k < 8; k++) { h0[k] = 0.f; h1[k] = 0.f; }

            #pragma unroll 4
            for (int r4 = 0; r4 < 8; r4++) {
                float4 ra = *(const float4*)&sRBF[b0 * 36 + r4 * 4];
                float4 rb = *(const float4*)&sRBF[(b0 + 1) * 36 + r4 * 4];
                float ras[4] = {ra.x, ra.y, ra.z, ra.w};
                float rbs[4] = {rb.x, rb.y, rb.z, rb.w};
                #pragma unroll
                for (int j = 0; j < 4; j++) {
                    int r = r4 * 4 + j;
                    float4 wlo = *(const float4*)&sW1[r * 68 + f0s];
                    float4 whi = *(const float4*)&sW1[r * 68 + f0s + 4];
                    float ws[8] = {wlo.x, wlo.y, wlo.z, wlo.w, whi.x, whi.y, whi.z, whi.w};
                    #pragma unroll
                    for (int k = 0; k < 8; k++) {
                        h0[k] = fmaf(ras[j], ws[k], h0[k]);
                        h1[k] = fmaf(rbs[j], ws[k], h1[k]);
                    }
                }
            }
            float4 blo = *(const float4*)&sB1[f0];
            float4 bhi = *(const float4*)&sB1[f0 + 4];
            float bs[8] = {blo.x, blo.y, blo.z, blo.w, bhi.x, bhi.y, bhi.z, bhi.w};
            float4 s0lo, s0hi, s1lo, s1hi;
            s0lo.x = fmaxf(h0[0] + bs[0], 0.f); s0lo.y = fmaxf(h0[1] + bs[1], 0.f);
            s0lo.z = fmaxf(h0[2] + bs[2], 0.f); s0lo.w = fmaxf(h0[3] + bs[3], 0.f);
            s0hi.x = fmaxf(h0[4] + bs[4], 0.f); s0hi.y = fmaxf(h0[5] + bs[5], 0.f);
            s0hi.z = fmaxf(h0[6] + bs[6], 0.f); s0hi.w = fmaxf(h0[7] + bs[7], 0.f);
            s1lo.x = fmaxf(h1[0] + bs[0], 0.f); s1lo.y = fmaxf(h1[1] + bs[1], 0.f);
            s1lo.z = fmaxf(h1[2] + bs[2], 0.f); s1lo.w = fmaxf(h1[3] + bs[3], 0.f);
            s1hi.x = fmaxf(h1[4] + bs[4], 0.f); s1hi.y = fmaxf(h1[5] + bs[5], 0.f);
            s1hi.z = fmaxf(h1[6] + bs[6], 0.f); s1hi.w = fmaxf(h1[7] + bs[7], 0.f);
            *(float4*)&sH[b0 * 68 + f0s]           = s0lo;
            *(float4*)&sH[b0 * 68 + f0s + 4]       = s0hi;
            *(float4*)&sH[(b0 + 1) * 68 + f0s]     = s1lo;
            *(float4*)&sH[(b0 + 1) * 68 + f0s + 4] = s1hi;
        }
        __syncthreads();

        // ---- GEMM2: rad[b][f] = H[b,:] @ W2 (+ b2 in epilogue) ----
        float r2[2][8];
        #pragma unroll
        for (int k = 0; k < 8; k++) { r2[0][k] = 0.f; r2[1][k] = 0.f; }

        #pragma unroll 4
        for (int c4 = 0; c4 < 16; c4++) {
            int cb = c4 * 4;
            int cbs = SW(cb);   // cb multiple of 4 -> 4 elems contiguous
            float4 ha = *(const float4*)&sH[b0 * 68 + cbs];
            float4 hb = *(const float4*)&sH[(b0 + 1) * 68 + cbs];
            float has[4] = {ha.x, ha.y, ha.z, ha.w};
            float hbs[4] = {hb.x, hb.y, hb.z, hb.w};
            #pragma unroll
            for (int j = 0; j < 4; j++) {
                int c = cb + j;
                float4 wlo = *(const float4*)&sW2[c * 68 + f0s];
                float4 whi = *(const float4*)&sW2[c * 68 + f0s + 4];
                float ws[8] = {wlo.x, wlo.y, wlo.z, wlo.w, whi.x, whi.y, whi.z, whi.w};
                #pragma unroll
                for (int k = 0; k < 8; k++) {
                    r2[0][k] = fmaf(has[j], ws[k], r2[0][k]);
                    r2[1][k] = fmaf(hbs[j], ws[k], r2[1][k]);
                }
            }
        }

        // ---- fused CG contraction (per m) ----
        float4 b2lo = *(const float4*)&sB2[f0];
        float4 b2hi = *(const float4*)&sB2[f0 + 4];
        float bvv[8] = {b2lo.x, b2lo.y, b2lo.z, b2lo.w, b2hi.x, b2hi.y, b2hi.z, b2hi.w};

        #pragma unroll
        for (int bi = 0; bi < 2; bi++) {
            const int bl = b0 + bi;
            if (bt + bl == a) continue;   // diagonal mask (zeroes biased rad)
            const float u0 = sU[bl * 4 + 0];
            const float u1 = sU[bl * 4 + 1];
            const float u2 = sU[bl * 4 + 2];

            if (m <= 1) {
                float4 xlo = *(const float4*)&sX0[bl * 68 + f0s];
                float4 xhi = *(const float4*)&sX0[bl * 68 + f0s + 4];
                float xs[8] = {xlo.x, xlo.y, xlo.z, xlo.w, xhi.x, xhi.y, xhi.z, xhi.w};
                if (m == 0) {
                    #pragma unroll
                    for (int k = 0; k < 8; k++)
                        acc[k][0] = fmaf(r2[bi][k] + bvv[k], xs[k], acc[k][0]);
                } else {
                    #pragma unroll
                    for (int k = 0; k < 8; k++) {
                        float t = (r2[bi][k] + bvv[k]) * xs[k];
                        acc[k][0] = fmaf(u0, t, acc[k][0]);
                        acc[k][1] = fmaf(u1, t, acc[k][1]);
                        acc[k][2] = fmaf(u2, t, acc[k][2]);
                    }
                }
            } else {
                float4 xxl = *(const float4*)&sX1[0 * 2176 + bl * 68 + f0s];
                float4 xxh = *(const float4*)&sX1[0 * 2176 + bl * 68 + f0s + 4];
                float4 xyl = *(const float4*)&sX1[1 * 2176 + bl * 68 + f0s];
                float4 xyh = *(const float4*)&sX1[1 * 2176 + bl * 68 + f0s + 4];
                float4 xzl = *(const float4*)&sX1[2 * 2176 + bl * 68 + f0s];
                float4 xzh = *(const float4*)&sX1[2 * 2176 + bl * 68 + f0s + 4];
                float xxs[8] = {xxl.x, xxl.y, xxl.z, xxl.w, xxh.x, xxh.y, xxh.z, xxh.w};
                float xys[8] = {xyl.x, xyl.y, xyl.z, xyl.w, xyh.x, xyh.y, xyh.z, xyh.w};
                float xzs[8] = {xzl.x, xzl.y, xzl.z, xzl.w, xzh.x, xzh.y, xzh.z, xzh.w};
                if (m == 2) {
                    #pragma unroll
                    for (int k = 0; k < 8; k++) {
                        float rad = r2[bi][k] + bvv[k];
                        acc[k][0] = fmaf(rad, xxs[k], acc[k][0]);
                        acc[k][1] = fmaf(rad, xys[k], acc[k][1]);
                        acc[k][2] = fmaf(rad, xzs[k], acc[k][2]);
                    }
                } else if (m == 3) {
                    #pragma unroll
                    for (int k = 0; k < 8; k++) {
                        float dot = u0 * xxs[k] + u1 * xys[k] + u2 * xzs[k];
                        acc[k][0] = fmaf(r2[bi][k] + bvv[k], dot, acc[k][0]);
                    }
                } else {   // m == 4 : cross product u x x1
                    #pragma unroll
                    for (int k = 0; k < 8; k++) {
                        float rad = r2[bi][k] + bvv[k];
                        float cx = u1 * xzs[k] - u2 * xys[k];
                        float cy = u2 * xxs[k] - u0 * xzs[k];
                        float cz = u0 * xys[k] - u1 * xxs[k];
                        acc[k][0] = fmaf(rad, cx, acc[k][0]);
                        acc[k][1] = fmaf(rad, cy, acc[k][1]);
                        acc[k][2] = fmaf(rad, cz, acc[k][2]);
                    }
                }
            }
        }
    }

    // ---- cross-thread reduction over the 16 b-groups ----
    __syncthreads();
    float* sPart = sW2;   // W2 dead; need 128*24 = 3072 <= 4352 floats
    {
        const int base = tid * 24;
        #pragma unroll
        for (int k = 0; k < 8; k++) {
            sPart[base + k * 3 + 0] = acc[k][0];
            sPart[base + k * 3 + 1] = acc[k][1];
            sPart[base + k * 3 + 2] = acc[k][2];
        }
    }
    __syncthreads();

    const float nm = rsqrtf((float)(NN - 1));
    float* out1 = out + NN * 2 * CC;

    for (int idx = tid; idx < CC * 3; idx += NT) {
        const int f    = idx / 3;
        const int comp = idx - f * 3;
        const int fb2  = f >> 3;
        const int k    = f & 7;
        float s = 0.0f;
        #pragma unroll
        for (int g = 0; g < 16; g++)
            s += sPart[(g * 8 + fb2) * 24 + k * 3 + comp];
        s *= nm;

        if (m == 0)      { if (comp == 0) out[a * 128 + f] = s; }            // o00
        else if (m == 1) { out1[a * 576 + f * 3 + comp] = s; }               // o01
        else if (m == 2) { out1[a * 576 + (64 + f) * 3 + comp] = s; }        // o10
        else if (m == 3) { if (comp == 0) out[a * 128 + 64 + f] = s; }       // o11_0
        else             { out1[a * 576 + (128 + f) * 3 + comp] = s; }       // o11_1
    }
}

extern "C" void kernel_launch(void* const* d_in, const int* in_sizes, int n_in,
                              void* d_out, int out_size) {
    const float* x0  = (const float*)d_in[0];
    const float* x1  = (const float*)d_in[1];
    const float* rbf = (const float*)d_in[2];
    const float* u   = (const float*)d_in[3];
    // d_in[4] = r_ij : unused (switching_fn == None)
    const float* w1  = (const float*)d_in[5];
    const float* b1  = (const float*)d_in[6];
    const float* w2  = (const float*)d_in[7];
    const float* b2  = (const float*)d_in[8];
    float* out = (float*)d_out;

    cudaFuncSetAttribute(conv_tfn_m_kernel,
                         cudaFuncAttributeMaxDynamicSharedMemorySize, SMEM_BYTES);

    dim3 grid(NN, 5);
    conv_tfn_m_kernel<<<grid, NT, SMEM_BYTES>>>(x0, x1, rbf, u, w1, b1, w2, b2, out);
}

// round 6
// speedup vs baseline: 2.5401x; 2.5401x over previous
#include <cuda_runtime.h>
#include <cstdint>

// Problem constants
#define NN 512
#define CC 64
#define RR 32
#define BT 32
#define NT 128

// smem layout (float units)
#define OFF_W1   0        // [32][72] tf32 bits   = 2304
#define OFF_W2   2304     // [64][72] tf32 bits   = 4608
#define OFF_RBF  6912     // [32][36] tf32 bits   = 1152
#define OFF_H    8064     // [32][68] tf32 bits   = 2176
#define OFF_X0   10240    // [32][68] fp32        = 2176
#define OFF_X1   12416    // [32][200] fp32       = 6400  (reused as sPart)
#define OFF_U    18816    // [32][4] fp32         = 128
#define SMEM_FLOATS 18944
#define SMEM_BYTES (SMEM_FLOATS * 4)   // 75776 B -> 3 CTAs/SM

extern __shared__ float smem[];

__device__ __forceinline__ uint32_t f2tf(float x) {
    uint32_t u;
    asm("cvt.rna.tf32.f32 %0, %1;" : "=r"(u) : "f"(x));
    return u;
}

__device__ __forceinline__ void mma_tf32(float c[4], const uint32_t a[4],
                                         uint32_t b0, uint32_t b1) {
    asm volatile(
        "mma.sync.aligned.m16n8k8.row.col.f32.tf32.tf32.f32 "
        "{%0,%1,%2,%3}, {%4,%5,%6,%7}, {%8,%9}, {%0,%1,%2,%3};"
        : "+f"(c[0]), "+f"(c[1]), "+f"(c[2]), "+f"(c[3])
        : "r"(a[0]), "r"(a[1]), "r"(a[2]), "r"(a[3]), "r"(b0), "r"(b1));
}

__global__ __launch_bounds__(NT, 3)
void conv_tfn_tc_kernel(const float* __restrict__ gx0,
                        const float* __restrict__ gx1,
                        const float* __restrict__ grbf,
                        const float* __restrict__ gu,
                        const float* __restrict__ gw1,
                        const float* __restrict__ gb1,
                        const float* __restrict__ gw2,
                        const float* __restrict__ gb2,
                        float* __restrict__ out)
{
    const int a    = blockIdx.x;
    const int m    = blockIdx.y;
    const int tid  = threadIdx.x;
    const int w    = tid >> 5;
    const int lane = tid & 31;
    const int mt    = w >> 1;        // row-tile of 16 (0..1)
    const int nhalf = w & 1;         // column half (0..1)
    const int r0    = lane >> 2;     // 0..7
    const int cpos  = lane & 3;      // 0..3

    uint32_t* sW1u  = (uint32_t*)(smem + OFF_W1);
    uint32_t* sW2u  = (uint32_t*)(smem + OFF_W2);
    uint32_t* sRBFu = (uint32_t*)(smem + OFF_RBF);
    uint32_t* sHu   = (uint32_t*)(smem + OFF_H);
    float*    sX0   = smem + OFF_X0;
    float*    sX1   = smem + OFF_X1;
    float*    sU    = smem + OFF_U;

    // ---- stage weights as tf32 (once per block) ----
    {
        const float* p = gw1 + (size_t)m * RR * CC;
        for (int i = tid; i < RR * CC; i += NT) {
            int r = i >> 6, f = i & 63;
            sW1u[r * 72 + f] = f2tf(p[i]);
        }
        const float* q = gw2 + (size_t)m * CC * CC;
        for (int i = tid; i < CC * CC; i += NT) {
            int c = i >> 6, f = i & 63;
            sW2u[c * 72 + f] = f2tf(q[i]);
        }
    }

    // ---- per-thread bias registers for the 8 owned columns ----
    float b1r[8], b2r[8];
    #pragma unroll
    for (int q = 0; q < 8; q++) {
        int f = nhalf * 32 + (q >> 1) * 8 + cpos * 2 + (q & 1);
        b1r[q] = gb1[m * CC + f];
        b2r[q] = gb2[m * CC + f];
    }

    float acc[8][3];
    #pragma unroll
    for (int q = 0; q < 8; q++) { acc[q][0] = 0.f; acc[q][1] = 0.f; acc[q][2] = 0.f; }

    const int rowA = mt * 16 + r0;   // this thread's first M-row within the tile

    for (int bt = 0; bt < NN; bt += BT) {
        __syncthreads();   // previous tile's consumers done

        // ---- stage rbf tile as tf32: [32][36] ----
        {
            const float4* p = (const float4*)(grbf + (size_t)a * NN * RR + (size_t)bt * RR);
            for (int i = tid; i < BT * RR / 4; i += NT) {   // 256 float4
                int row = i >> 3, p4 = i & 7;
                float4 v = p[i];
                uint32_t* d = &sRBFu[row * 36 + p4 * 4];
                d[0] = f2tf(v.x); d[1] = f2tf(v.y); d[2] = f2tf(v.z); d[3] = f2tf(v.w);
            }
        }
        // ---- stage x0 (m<=1) or x1 (m>=2), fp32, layout preserved ----
        if (m <= 1) {
            const float4* p = (const float4*)(gx0 + (size_t)bt * CC);
            for (int i = tid; i < BT * CC / 4; i += NT) {   // 512 float4
                int row = i >> 4, pos = i & 15;
                *(float4*)&sX0[row * 68 + pos * 4] = p[i];
            }
        } else {
            const float4* p = (const float4*)(gx1 + (size_t)bt * CC * 3);
            for (int i = tid; i < BT * CC * 3 / 4; i += NT) {  // 1536 float4
                int row = i / 48, pos = i - row * 48;
                *(float4*)&sX1[row * 200 + pos * 4] = p[i];
            }
        }
        if (tid < BT * 3) {
            int row = tid / 3, c = tid - row * 3;
            sU[row * 4 + c] = gu[(size_t)a * NN * 3 + (size_t)bt * 3 + tid];
        }
        __syncthreads();

        // ---- GEMM1 (tensor): H = relu(rbf @ W1 + b1), tf32 in / fp32 acc ----
        float hc[4][4];
        #pragma unroll
        for (int nt = 0; nt < 4; nt++)
            #pragma unroll
            for (int j = 0; j < 4; j++) hc[nt][j] = 0.f;

        #pragma unroll
        for (int kk = 0; kk < 4; kk++) {
            uint32_t A[4];
            A[0] = sRBFu[rowA * 36 + kk * 8 + cpos];
            A[1] = sRBFu[(rowA + 8) * 36 + kk * 8 + cpos];
            A[2] = sRBFu[rowA * 36 + kk * 8 + cpos + 4];
            A[3] = sRBFu[(rowA + 8) * 36 + kk * 8 + cpos + 4];
            #pragma unroll
            for (int nt = 0; nt < 4; nt++) {
                int n = nhalf * 32 + nt * 8 + r0;
                uint32_t B0 = sW1u[(kk * 8 + cpos) * 72 + n];
                uint32_t B1 = sW1u[(kk * 8 + cpos + 4) * 72 + n];
                mma_tf32(hc[nt], A, B0, B1);
            }
        }
        // epilogue: bias + relu + cvt -> sH
        #pragma unroll
        for (int nt = 0; nt < 4; nt++) {
            int col0 = nhalf * 32 + nt * 8 + cpos * 2;
            sHu[rowA * 68 + col0]           = f2tf(fmaxf(hc[nt][0] + b1r[nt * 2], 0.f));
            sHu[rowA * 68 + col0 + 1]       = f2tf(fmaxf(hc[nt][1] + b1r[nt * 2 + 1], 0.f));
            sHu[(rowA + 8) * 68 + col0]     = f2tf(fmaxf(hc[nt][2] + b1r[nt * 2], 0.f));
            sHu[(rowA + 8) * 68 + col0 + 1] = f2tf(fmaxf(hc[nt][3] + b1r[nt * 2 + 1], 0.f));
        }
        __syncthreads();

        // ---- GEMM2 (tensor): rad = H @ W2 ----
        float rc[4][4];
        #pragma unroll
        for (int nt = 0; nt < 4; nt++)
            #pragma unroll
            for (int j = 0; j < 4; j++) rc[nt][j] = 0.f;

        #pragma unroll
        for (int kk = 0; kk < 8; kk++) {
            uint32_t A[4];
            A[0] = sHu[rowA * 68 + kk * 8 + cpos];
            A[1] = sHu[(rowA + 8) * 68 + kk * 8 + cpos];
            A[2] = sHu[rowA * 68 + kk * 8 + cpos + 4];
            A[3] = sHu[(rowA + 8) * 68 + kk * 8 + cpos + 4];
            #pragma unroll
            for (int nt = 0; nt < 4; nt++) {
                int n = nhalf * 32 + nt * 8 + r0;
                uint32_t B0 = sW2u[(kk * 8 + cpos) * 72 + n];
                uint32_t B1 = sW2u[(kk * 8 + cpos + 4) * 72 + n];
                mma_tf32(rc[nt], A, B0, B1);
            }
        }

        // ---- fused CG contraction (fp32 CUDA cores) ----
        #pragma unroll
        for (int rs = 0; rs < 2; rs++) {
            const int row = rowA + rs * 8;
            if (bt + row == a) continue;   // diagonal mask
            float u0 = 0.f, u1 = 0.f, u2 = 0.f;
            if (m == 1 || m >= 3) {
                u0 = sU[row * 4 + 0]; u1 = sU[row * 4 + 1]; u2 = sU[row * 4 + 2];
            }
            #pragma unroll
            for (int nt = 0; nt < 4; nt++) {
                #pragma unroll
                for (int j = 0; j < 2; j++) {
                    const int q = nt * 2 + j;
                    const int f = nhalf * 32 + nt * 8 + cpos * 2 + j;
                    const float rad = rc[nt][rs * 2 + j] + b2r[q];
                    if (m == 0) {
                        acc[q][0] = fmaf(rad, sX0[row * 68 + f], acc[q][0]);
                    } else if (m == 1) {
                        float t = rad * sX0[row * 68 + f];
                        acc[q][0] = fmaf(u0, t, acc[q][0]);
                        acc[q][1] = fmaf(u1, t, acc[q][1]);
                        acc[q][2] = fmaf(u2, t, acc[q][2]);
                    } else {
                        float xx = sX1[row * 200 + 3 * f + 0];
                        float xy = sX1[row * 200 + 3 * f + 1];
                        float xz = sX1[row * 200 + 3 * f + 2];
                        if (m == 2) {
                            acc[q][0] = fmaf(rad, xx, acc[q][0]);
                            acc[q][1] = fmaf(rad, xy, acc[q][1]);
                            acc[q][2] = fmaf(rad, xz, acc[q][2]);
                        } else if (m == 3) {
                            float dot = u0 * xx + u1 * xy + u2 * xz;
                            acc[q][0] = fmaf(rad, dot, acc[q][0]);
                        } else {
                            float cx = u1 * xz - u2 * xy;
                            float cy = u2 * xx - u0 * xz;
                            float cz = u0 * xy - u1 * xx;
                            acc[q][0] = fmaf(rad, cx, acc[q][0]);
                            acc[q][1] = fmaf(rad, cy, acc[q][1]);
                            acc[q][2] = fmaf(rad, cz, acc[q][2]);
                        }
                    }
                }
            }
        }
    }

    // ---- cross-thread reduction (16 contributors per output column) ----
    __syncthreads();
    float* sPart = smem + OFF_X1;   // x1 region dead; need 128*24 = 3072 floats
    {
        const int base = tid * 24;
        #pragma unroll
        for (int q = 0; q < 8; q++) {
            sPart[base + q * 3 + 0] = acc[q][0];
            sPart[base + q * 3 + 1] = acc[q][1];
            sPart[base + q * 3 + 2] = acc[q][2];
        }
    }
    __syncthreads();

    const float nm = rsqrtf((float)(NN - 1));
    float* out1 = out + NN * 2 * CC;

    for (int idx = tid; idx < CC * 3; idx += NT) {
        const int f    = idx / 3;
        const int comp = idx - f * 3;
        const int nh = f >> 5;
        const int nt = (f >> 3) & 3;
        const int cp = (f & 7) >> 1;
        const int j  = f & 1;
        const int q  = nt * 2 + j;
        float s = 0.0f;
        #pragma unroll
        for (int ww = 0; ww < 2; ww++) {
            int wv = nh + ww * 2;
            #pragma unroll
            for (int rg = 0; rg < 8; rg++) {
                int tc = wv * 32 + rg * 4 + cp;
                s += sPart[tc * 24 + q * 3 + comp];
            }
        }
        s *= nm;

        if (m == 0)      { if (comp == 0) out[a * 128 + f] = s; }
        else if (m == 1) { out1[a * 576 + f * 3 + comp] = s; }
        else if (m == 2) { out1[a * 576 + (64 + f) * 3 + comp] = s; }
        else if (m == 3) { if (comp == 0) out[a * 128 + 64 + f] = s; }
        else             { out1[a * 576 + (128 + f) * 3 + comp] = s; }
    }
}

extern "C" void kernel_launch(void* const* d_in, const int* in_sizes, int n_in,
                              void* d_out, int out_size) {
    const float* x0  = (const float*)d_in[0];
    const float* x1  = (const float*)d_in[1];
    const float* rbf = (const float*)d_in[2];
    const float* u   = (const float*)d_in[3];
    // d_in[4] = r_ij : unused (switching_fn == None)
    const float* w1  = (const float*)d_in[5];
    const float* b1  = (const float*)d_in[6];
    const float* w2  = (const float*)d_in[7];
    const float* b2  = (const float*)d_in[8];
    float* out = (float*)d_out;

    cudaFuncSetAttribute(conv_tfn_tc_kernel,
                         cudaFuncAttributeMaxDynamicSharedMemorySize, SMEM_BYTES);

    dim3 grid(NN, 5);
    conv_tfn_tc_kernel<<<grid, NT, SMEM_BYTES>>>(x0, x1, rbf, u, w1, b1, w2, b2, out);
}

// round 7
// speedup vs baseline: 2.6344x; 1.0371x over previous
#include <cuda_runtime.h>
#include <cstdint>

#define NN 512
#define CC 64
#define RR 32
#define BT 64
#define NT 256

// permuted-k column maps: thread cpos reads k ≡ cpos (mod 4) contiguously
#define PC1(k) (((k) & 3) * 8 + ((k) >> 2))    // k<32, row width 32+pad -> stride 36
#define PC2(k) (((k) & 3) * 20 + ((k) >> 2))   // k<64, row width 80 (stride 80)

// smem layout (float units)
#define OFF_W1   0        // [64 n][36]  = 2304 (tf32, pc1)
#define OFF_W2   2304     // [64 n][80]  = 5120 (tf32, pc2)
#define OFF_RBF  7424     // [64 b][36]  = 2304 (tf32, pc1)
#define OFF_H    9728     // [64 b][80]  = 5120 (tf32, pc2)
#define OFF_X    14848    // x1:[64][200]=12800 | x0:[64][68] | sPart overlay
#define OFF_U    27648    // [64][4] = 256
#define SMEM_FLOATS 27904
#define SMEM_BYTES (SMEM_FLOATS * 4)   // 111616 B -> 2 CTAs/SM

extern __shared__ float smem[];

__device__ __forceinline__ uint32_t f2tf(float x) {
    uint32_t u;
    asm("cvt.rna.tf32.f32 %0, %1;" : "=r"(u) : "f"(x));
    return u;
}

__device__ __forceinline__ void mma_tf32(float c[4], uint32_t a0, uint32_t a1,
                                         uint32_t a2, uint32_t a3,
                                         uint32_t b0, uint32_t b1) {
    asm volatile(
        "mma.sync.aligned.m16n8k8.row.col.f32.tf32.tf32.f32 "
        "{%0,%1,%2,%3}, {%4,%5,%6,%7}, {%8,%9}, {%0,%1,%2,%3};"
        : "+f"(c[0]), "+f"(c[1]), "+f"(c[2]), "+f"(c[3])
        : "r"(a0), "r"(a1), "r"(a2), "r"(a3), "r"(b0), "r"(b1));
}

__global__ __launch_bounds__(NT, 2)
void conv_tfn_tc2_kernel(const float* __restrict__ gx0,
                         const float* __restrict__ gx1,
                         const float* __restrict__ grbf,
                         const float* __restrict__ gu,
                         const float* __restrict__ gw1,
                         const float* __restrict__ gb1,
                         const float* __restrict__ gw2,
                         const float* __restrict__ gb2,
                         float* __restrict__ out)
{
    const int a    = blockIdx.x;
    const int m    = blockIdx.y;
    const int tid  = threadIdx.x;
    const int w    = tid >> 5;
    const int lane = tid & 31;
    const int mt    = w >> 1;        // row-tile of 16 (0..3)
    const int nhalf = w & 1;         // column half (0..1)
    const int r0    = lane >> 2;     // 0..7
    const int cpos  = lane & 3;      // 0..3

    uint32_t* sW1u  = (uint32_t*)(smem + OFF_W1);
    uint32_t* sW2u  = (uint32_t*)(smem + OFF_W2);
    uint32_t* sRBFu = (uint32_t*)(smem + OFF_RBF);
    uint32_t* sHu   = (uint32_t*)(smem + OFF_H);
    float*    sX    = smem + OFF_X;
    float*    sU    = smem + OFF_U;

    // ---- stage weights as tf32 in permuted-k layout (once per block) ----
    {
        const float* p = gw1 + (size_t)m * RR * CC;
        for (int i = tid; i < RR * CC; i += NT) {
            int k = i >> 6, n = i & 63;
            sW1u[n * 36 + PC1(k)] = f2tf(p[i]);
        }
        const float* q = gw2 + (size_t)m * CC * CC;
        for (int i = tid; i < CC * CC; i += NT) {
            int k = i >> 6, n = i & 63;
            sW2u[n * 80 + PC2(k)] = f2tf(q[i]);
        }
    }

    // ---- per-thread bias registers for the 8 owned columns ----
    float b1r[8], b2r[8];
    #pragma unroll
    for (int q = 0; q < 8; q++) {
        int f = nhalf * 32 + (q >> 1) * 8 + cpos * 2 + (q & 1);
        b1r[q] = gb1[m * CC + f];
        b2r[q] = gb2[m * CC + f];
    }

    float acc[8][3];
    #pragma unroll
    for (int q = 0; q < 8; q++) { acc[q][0] = 0.f; acc[q][1] = 0.f; acc[q][2] = 0.f; }

    const int rowA = mt * 16 + r0;

    for (int bt = 0; bt < NN; bt += BT) {
        __syncthreads();

        // ---- stage rbf tile (tf32, pc1) ----
        {
            const float4* p = (const float4*)(grbf + (size_t)a * NN * RR + (size_t)bt * RR);
            #pragma unroll
            for (int t = 0; t < 2; t++) {                 // 512 float4 total
                int i = tid + t * NT;
                float4 v = p[i];
                int row = i >> 3, kb = (i & 7) * 4;
                uint32_t* d = &sRBFu[row * 36];
                d[PC1(kb + 0)] = f2tf(v.x);
                d[PC1(kb + 1)] = f2tf(v.y);
                d[PC1(kb + 2)] = f2tf(v.z);
                d[PC1(kb + 3)] = f2tf(v.w);
            }
        }
        // ---- stage x0 (m<=1, stride 68) or x1 (m>=2, stride 200) ----
        if (m <= 1) {
            const float4* p = (const float4*)(gx0 + (size_t)bt * CC);
            #pragma unroll
            for (int t = 0; t < 4; t++) {                 // 1024 float4
                int i = tid + t * NT;
                int row = i >> 4, pos = i & 15;
                *(float4*)&sX[row * 68 + pos * 4] = p[i];
            }
        } else {
            const float4* p = (const float4*)(gx1 + (size_t)bt * CC * 3);
            #pragma unroll
            for (int t = 0; t < 12; t++) {                // 3072 float4
                int i = tid + t * NT;
                int row = i / 48, pos = i - row * 48;
                *(float4*)&sX[row * 200 + pos * 4] = p[i];
            }
        }
        if (tid < BT * 3) {
            int row = tid / 3, c = tid - row * 3;
            sU[row * 4 + c] = gu[(size_t)a * NN * 3 + (size_t)bt * 3 + tid];
        }
        __syncthreads();

        // ---- GEMM1 (tensor): H = relu(rbf @ W1 + b1) ----
        float hc[4][4];
        #pragma unroll
        for (int nt = 0; nt < 4; nt++)
            #pragma unroll
            for (int j = 0; j < 4; j++) hc[nt][j] = 0.f;

        {
            uint32_t A0[8], A1[8];
            *(uint4*)&A0[0] = *(const uint4*)&sRBFu[rowA * 36 + cpos * 8];
            *(uint4*)&A0[4] = *(const uint4*)&sRBFu[rowA * 36 + cpos * 8 + 4];
            *(uint4*)&A1[0] = *(const uint4*)&sRBFu[(rowA + 8) * 36 + cpos * 8];
            *(uint4*)&A1[4] = *(const uint4*)&sRBFu[(rowA + 8) * 36 + cpos * 8 + 4];
            #pragma unroll
            for (int nt = 0; nt < 4; nt++) {
                const int n = nhalf * 32 + nt * 8 + r0;
                uint32_t B[8];
                *(uint4*)&B[0] = *(const uint4*)&sW1u[n * 36 + cpos * 8];
                *(uint4*)&B[4] = *(const uint4*)&sW1u[n * 36 + cpos * 8 + 4];
                #pragma unroll
                for (int kk = 0; kk < 4; kk++)
                    mma_tf32(hc[nt], A0[2*kk], A1[2*kk], A0[2*kk+1], A1[2*kk+1],
                             B[2*kk], B[2*kk+1]);
            }
        }
        // epilogue: bias + relu + cvt -> sH (pc2 layout)
        #pragma unroll
        for (int nt = 0; nt < 4; nt++) {
            #pragma unroll
            for (int j = 0; j < 2; j++) {
                int col = nhalf * 32 + nt * 8 + cpos * 2 + j;
                int pc = PC2(col);
                sHu[rowA * 80 + pc]       = f2tf(fmaxf(hc[nt][j]     + b1r[nt*2+j], 0.f));
                sHu[(rowA + 8) * 80 + pc] = f2tf(fmaxf(hc[nt][2 + j] + b1r[nt*2+j], 0.f));
            }
        }
        __syncthreads();

        // ---- GEMM2 (tensor): rad = H @ W2 ----
        float rc[4][4];
        #pragma unroll
        for (int nt = 0; nt < 4; nt++)
            #pragma unroll
            for (int j = 0; j < 4; j++) rc[nt][j] = 0.f;

        {
            uint32_t A0[16], A1[16];
            #pragma unroll
            for (int t = 0; t < 4; t++) {
                *(uint4*)&A0[t*4] = *(const uint4*)&sHu[rowA * 80 + cpos * 20 + t * 4];
                *(uint4*)&A1[t*4] = *(const uint4*)&sHu[(rowA + 8) * 80 + cpos * 20 + t * 4];
            }
            #pragma unroll
            for (int nt = 0; nt < 4; nt++) {
                const int n = nhalf * 32 + nt * 8 + r0;
                uint32_t B[16];
                #pragma unroll
                for (int t = 0; t < 4; t++)
                    *(uint4*)&B[t*4] = *(const uint4*)&sW2u[n * 80 + cpos * 20 + t * 4];
                #pragma unroll
                for (int kk = 0; kk < 8; kk++)
                    mma_tf32(rc[nt], A0[2*kk], A1[2*kk], A0[2*kk+1], A1[2*kk+1],
                             B[2*kk], B[2*kk+1]);
            }
        }

        // ---- fused CG contraction (fp32) ----
        #pragma unroll
        for (int rs = 0; rs < 2; rs++) {
            const int row = rowA + rs * 8;
            if (bt + row == a) continue;   // diagonal mask
            float u0 = 0.f, u1 = 0.f, u2 = 0.f;
            if (m == 1 || m >= 3) {
                u0 = sU[row * 4 + 0]; u1 = sU[row * 4 + 1]; u2 = sU[row * 4 + 2];
            }
            #pragma unroll
            for (int nt = 0; nt < 4; nt++) {
                #pragma unroll
                for (int j = 0; j < 2; j++) {
                    const int q = nt * 2 + j;
                    const int f = nhalf * 32 + nt * 8 + cpos * 2 + j;
                    const float rad = rc[nt][rs * 2 + j] + b2r[q];
                    if (m == 0) {
                        acc[q][0] = fmaf(rad, sX[row * 68 + f], acc[q][0]);
                    } else if (m == 1) {
                        float t = rad * sX[row * 68 + f];
                        acc[q][0] = fmaf(u0, t, acc[q][0]);
                        acc[q][1] = fmaf(u1, t, acc[q][1]);
                        acc[q][2] = fmaf(u2, t, acc[q][2]);
                    } else {
                        float xx = sX[row * 200 + 3 * f + 0];
                        float xy = sX[row * 200 + 3 * f + 1];
                        float xz = sX[row * 200 + 3 * f + 2];
                        if (m == 2) {
                            acc[q][0] = fmaf(rad, xx, acc[q][0]);
                            acc[q][1] = fmaf(rad, xy, acc[q][1]);
                            acc[q][2] = fmaf(rad, xz, acc[q][2]);
                        } else if (m == 3) {
                            float dot = u0 * xx + u1 * xy + u2 * xz;
                            acc[q][0] = fmaf(rad, dot, acc[q][0]);
                        } else {
                            float cx = u1 * xz - u2 * xy;
                            float cy = u2 * xx - u0 * xz;
                            float cz = u0 * xy - u1 * xx;
                            acc[q][0] = fmaf(rad, cx, acc[q][0]);
                            acc[q][1] = fmaf(rad, cy, acc[q][1]);
                            acc[q][2] = fmaf(rad, cz, acc[q][2]);
                        }
                    }
                }
            }
        }
    }

    // ---- cross-thread reduction (32 contributors per output column) ----
    __syncthreads();
    float* sPart = smem + OFF_X;   // x region dead; need 256*24 = 6144 floats
    {
        const int base = tid * 24;
        #pragma unroll
        for (int q = 0; q < 8; q++) {
            sPart[base + q * 3 + 0] = acc[q][0];
            sPart[base + q * 3 + 1] = acc[q][1];
            sPart[base + q * 3 + 2] = acc[q][2];
        }
    }
    __syncthreads();

    const float nm = rsqrtf((float)(NN - 1));
    float* out1 = out + NN * 2 * CC;

    if (tid < CC * 3) {
        const int f    = tid / 3;
        const int comp = tid - f * 3;
        const int nh = f >> 5;
        const int nt = (f >> 3) & 3;
        const int cp = (f & 7) >> 1;
        const int j  = f & 1;
        const int q  = nt * 2 + j;
        float s = 0.0f;
        #pragma unroll
        for (int mm = 0; mm < 4; mm++) {
            #pragma unroll
            for (int rg = 0; rg < 8; rg++) {
                int tc = (mm * 2 + nh) * 32 + rg * 4 + cp;
                s += sPart[tc * 24 + q * 3 + comp];
            }
        }
        s *= nm;

        if (m == 0)      { if (comp == 0) out[a * 128 + f] = s; }
        else if (m == 1) { out1[a * 576 + f * 3 + comp] = s; }
        else if (m == 2) { out1[a * 576 + (64 + f) * 3 + comp] = s; }
        else if (m == 3) { if (comp == 0) out[a * 128 + 64 + f] = s; }
        else             { out1[a * 576 + (128 + f) * 3 + comp] = s; }
    }
}

extern "C" void kernel_launch(void* const* d_in, const int* in_sizes, int n_in,
                              void* d_out, int out_size) {
    const float* x0  = (const float*)d_in[0];
    const float* x1  = (const float*)d_in[1];
    const float* rbf = (const float*)d_in[2];
    const float* u   = (const float*)d_in[3];
    // d_in[4] = r_ij : unused (switching_fn == None)
    const float* w1  = (const float*)d_in[5];
    const float* b1  = (const float*)d_in[6];
    const float* w2  = (const float*)d_in[7];
    const float* b2  = (const float*)d_in[8];
    float* out = (float*)d_out;

    cudaFuncSetAttribute(conv_tfn_tc2_kernel,
                         cudaFuncAttributeMaxDynamicSharedMemorySize, SMEM_BYTES);

    dim3 grid(NN, 5);
    conv_tfn_tc2_kernel<<<grid, NT, SMEM_BYTES>>>(x0, x1, rbf, u, w1, b1, w2, b2, out);
}

// round 8
// speedup vs baseline: 3.0128x; 1.1436x over previous
#include <cuda_runtime.h>
#include <cstdint>

#define NN 512
#define CC 64
#define RR 32
#define BT 64
#define NT 256

// permuted-k column maps: thread cpos reads k ≡ cpos (mod 4) contiguously
#define PC1(k) (((k) & 3) * 8 + ((k) >> 2))    // k<32, row stride 36
#define PC2(k) (((k) & 3) * 20 + ((k) >> 2))   // k<64, row stride 80

// mma n-column for physical channel f (so each thread owns 8 contiguous f)
#define PERMN(f) (((f) & 32) + ((((f) & 7) >> 1) << 3) + ((((f) >> 3) & 3) << 1) + ((f) & 1))

// smem layout (float units)
#define OFF_W1   0        // [64 n][36]  = 2304 (tf32, pc1)   | sPart overlay (6144)
#define OFF_W2   2304     // [64 n][80]  = 5120 (tf32, pc2)   |
#define OFF_RBF  7424     // [64 b][36]  = 2304 (tf32, pc1)
#define OFF_H    9728     // [64 b][80]  = 5120 (tf32, pc2)
#define OFF_U    14848    // [192] linear
#define SMEM_FLOATS 15040
#define SMEM_BYTES (SMEM_FLOATS * 4)   // 60160 B

extern __shared__ float smem[];

__device__ __forceinline__ uint32_t f2tf(float x) {
    uint32_t u;
    asm("cvt.rna.tf32.f32 %0, %1;" : "=r"(u) : "f"(x));
    return u;
}

__device__ __forceinline__ void mma_tf32(float c[4], uint32_t a0, uint32_t a1,
                                         uint32_t a2, uint32_t a3,
                                         uint32_t b0, uint32_t b1) {
    asm volatile(
        "mma.sync.aligned.m16n8k8.row.col.f32.tf32.tf32.f32 "
        "{%0,%1,%2,%3}, {%4,%5,%6,%7}, {%8,%9}, {%0,%1,%2,%3};"
        : "+f"(c[0]), "+f"(c[1]), "+f"(c[2]), "+f"(c[3])
        : "r"(a0), "r"(a1), "r"(a2), "r"(a3), "r"(b0), "r"(b1));
}

__global__ __launch_bounds__(NT, 2)
void conv_tfn_tc3_kernel(const float* __restrict__ gx0,
                         const float* __restrict__ gx1,
                         const float* __restrict__ grbf,
                         const float* __restrict__ gu,
                         const float* __restrict__ gw1,
                         const float* __restrict__ gb1,
                         const float* __restrict__ gw2,
                         const float* __restrict__ gb2,
                         float* __restrict__ out)
{
    const int a    = blockIdx.x;
    const int m    = blockIdx.y;
    const int tid  = threadIdx.x;
    const int w    = tid >> 5;
    const int lane = tid & 31;
    const int mt    = w >> 1;        // row-tile of 16 (0..3)
    const int nhalf = w & 1;         // column half (0..1)
    const int r0    = lane >> 2;     // 0..7
    const int cpos  = lane & 3;      // 0..3

    uint32_t* sW1u  = (uint32_t*)(smem + OFF_W1);
    uint32_t* sW2u  = (uint32_t*)(smem + OFF_W2);
    uint32_t* sRBFu = (uint32_t*)(smem + OFF_RBF);
    uint32_t* sHu   = (uint32_t*)(smem + OFF_H);
    float*    sU    = smem + OFF_U;

    // ---- stage weights as tf32, permuted-k rows + permuted-n columns ----
    {
        const float* p = gw1 + (size_t)m * RR * CC;
        for (int i = tid; i < RR * CC; i += NT) {
            int k = i >> 6, f = i & 63;
            sW1u[PERMN(f) * 36 + PC1(k)] = f2tf(p[i]);
        }
        const float* q = gw2 + (size_t)m * CC * CC;
        for (int i = tid; i < CC * CC; i += NT) {
            int k = i >> 6, f = i & 63;              // k = physical hidden channel c
            sW2u[PERMN(f) * 80 + PC2(k)] = f2tf(q[i]);
        }
    }

    // this thread owns physical channels fbase..fbase+7 (contiguous)
    const int fbase = nhalf * 32 + cpos * 8;

    float b1r[8], b2r[8];
    {
        float4 t0 = *(const float4*)(gb1 + m * CC + fbase);
        float4 t1 = *(const float4*)(gb1 + m * CC + fbase + 4);
        b1r[0]=t0.x; b1r[1]=t0.y; b1r[2]=t0.z; b1r[3]=t0.w;
        b1r[4]=t1.x; b1r[5]=t1.y; b1r[6]=t1.z; b1r[7]=t1.w;
        float4 s0 = *(const float4*)(gb2 + m * CC + fbase);
        float4 s1 = *(const float4*)(gb2 + m * CC + fbase + 4);
        b2r[0]=s0.x; b2r[1]=s0.y; b2r[2]=s0.z; b2r[3]=s0.w;
        b2r[4]=s1.x; b2r[5]=s1.y; b2r[6]=s1.z; b2r[7]=s1.w;
    }

    float acc[8][3];
    #pragma unroll
    for (int q = 0; q < 8; q++) { acc[q][0] = 0.f; acc[q][1] = 0.f; acc[q][2] = 0.f; }

    const int rowA = mt * 16 + r0;

    for (int bt = 0; bt < NN; bt += BT) {
        __syncthreads();   // all warps done with previous tile (rbf/H/U reusable)

        // ---- stage rbf tile (tf32, pc1 layout) ----
        {
            const float4* p = (const float4*)(grbf + (size_t)a * NN * RR + (size_t)bt * RR);
            #pragma unroll
            for (int t = 0; t < 2; t++) {
                int i = tid + t * NT;
                float4 v = p[i];
                int row = i >> 3, kq = i & 7;        // kq = k/4
                uint32_t* d = &sRBFu[row * 36 + kq];
                d[0]  = f2tf(v.x);
                d[8]  = f2tf(v.y);
                d[16] = f2tf(v.z);
                d[24] = f2tf(v.w);
            }
        }
        // ---- stage u (linear float4 copy) ----
        if (tid < BT * 3 / 4)
            ((float4*)sU)[tid] = ((const float4*)(gu + (size_t)a * NN * 3 + (size_t)bt * 3))[tid];
        __syncthreads();

        // ---- GEMM1 (tensor): H = relu(rbf @ W1 + b1) ----
        float hc[4][4];
        #pragma unroll
        for (int nt = 0; nt < 4; nt++)
            #pragma unroll
            for (int j = 0; j < 4; j++) hc[nt][j] = 0.f;
        {
            uint32_t A0[8], A1[8];
            *(uint4*)&A0[0] = *(const uint4*)&sRBFu[rowA * 36 + cpos * 8];
            *(uint4*)&A0[4] = *(const uint4*)&sRBFu[rowA * 36 + cpos * 8 + 4];
            *(uint4*)&A1[0] = *(const uint4*)&sRBFu[(rowA + 8) * 36 + cpos * 8];
            *(uint4*)&A1[4] = *(const uint4*)&sRBFu[(rowA + 8) * 36 + cpos * 8 + 4];
            #pragma unroll
            for (int nt = 0; nt < 4; nt++) {
                const int n = nhalf * 32 + nt * 8 + r0;
                uint32_t B[8];
                *(uint4*)&B[0] = *(const uint4*)&sW1u[n * 36 + cpos * 8];
                *(uint4*)&B[4] = *(const uint4*)&sW1u[n * 36 + cpos * 8 + 4];
                #pragma unroll
                for (int kk = 0; kk < 4; kk++)
                    mma_tf32(hc[nt], A0[2*kk], A1[2*kk], A0[2*kk+1], A1[2*kk+1],
                             B[2*kk], B[2*kk+1]);
            }
        }
        // epilogue: bias + relu + cvt -> sH at physical channel c = fbase + nt*2 + j
        #pragma unroll
        for (int nt = 0; nt < 4; nt++) {
            #pragma unroll
            for (int j = 0; j < 2; j++) {
                int c  = fbase + nt * 2 + j;
                int pc = PC2(c);
                sHu[rowA * 80 + pc]       = f2tf(fmaxf(hc[nt][j]     + b1r[nt*2+j], 0.f));
                sHu[(rowA + 8) * 80 + pc] = f2tf(fmaxf(hc[nt][2 + j] + b1r[nt*2+j], 0.f));
            }
        }
        // H rows [mt*16, mt*16+16) are produced and consumed by this 2-warp pair only
        asm volatile("bar.sync %0, %1;" :: "r"(1 + mt), "r"(64) : "memory");

        // ---- GEMM2 (tensor): rad = H @ W2 ----
        float rc[4][4];
        #pragma unroll
        for (int nt = 0; nt < 4; nt++)
            #pragma unroll
            for (int j = 0; j < 4; j++) rc[nt][j] = 0.f;
        {
            uint32_t A0[16], A1[16];
            #pragma unroll
            for (int t = 0; t < 4; t++) {
                *(uint4*)&A0[t*4] = *(const uint4*)&sHu[rowA * 80 + cpos * 20 + t * 4];
                *(uint4*)&A1[t*4] = *(const uint4*)&sHu[(rowA + 8) * 80 + cpos * 20 + t * 4];
            }
            #pragma unroll
            for (int nt = 0; nt < 4; nt++) {
                const int n = nhalf * 32 + nt * 8 + r0;
                uint32_t B[16];
                #pragma unroll
                for (int t = 0; t < 4; t++)
                    *(uint4*)&B[t*4] = *(const uint4*)&sW2u[n * 80 + cpos * 20 + t * 4];
                #pragma unroll
                for (int kk = 0; kk < 8; kk++)
                    mma_tf32(rc[nt], A0[2*kk], A1[2*kk], A0[2*kk+1], A1[2*kk+1],
                             B[2*kk], B[2*kk+1]);
            }
        }

        // ---- fused CG contraction: x read directly from global (L2-resident) ----
        #pragma unroll
        for (int rs = 0; rs < 2; rs++) {
            const int row  = rowA + rs * 8;
            const int grow = bt + row;
            if (grow == a) continue;   // diagonal mask
            if (m <= 1) {
                float4 xa = *(const float4*)(gx0 + (size_t)grow * CC + fbase);
                float4 xb = *(const float4*)(gx0 + (size_t)grow * CC + fbase + 4);
                float xs[8] = {xa.x, xa.y, xa.z, xa.w, xb.x, xb.y, xb.z, xb.w};
                if (m == 0) {
                    #pragma unroll
                    for (int q = 0; q < 8; q++) {
                        float rad = rc[q >> 1][rs * 2 + (q & 1)] + b2r[q];
                        acc[q][0] = fmaf(rad, xs[q], acc[q][0]);
                    }
                } else {
                    float u0 = sU[row * 3 + 0], u1 = sU[row * 3 + 1], u2 = sU[row * 3 + 2];
                    #pragma unroll
                    for (int q = 0; q < 8; q++) {
                        float rad = rc[q >> 1][rs * 2 + (q & 1)] + b2r[q];
                        float t = rad * xs[q];
                        acc[q][0] = fmaf(u0, t, acc[q][0]);
                        acc[q][1] = fmaf(u1, t, acc[q][1]);
                        acc[q][2] = fmaf(u2, t, acc[q][2]);
                    }
                }
            } else {
                float xr[24];
                const float4* xp = (const float4*)(gx1 + (size_t)grow * CC * 3 + fbase * 3);
                #pragma unroll
                for (int t = 0; t < 6; t++)
                    *(float4*)&xr[t * 4] = xp[t];
                float u0 = 0.f, u1 = 0.f, u2 = 0.f;
                if (m >= 3) {
                    u0 = sU[row * 3 + 0]; u1 = sU[row * 3 + 1]; u2 = sU[row * 3 + 2];
                }
                #pragma unroll
                for (int q = 0; q < 8; q++) {
                    float rad = rc[q >> 1][rs * 2 + (q & 1)] + b2r[q];
                    float xx = xr[3 * q], xy = xr[3 * q + 1], xz = xr[3 * q + 2];
                    if (m == 2) {
                        acc[q][0] = fmaf(rad, xx, acc[q][0]);
                        acc[q][1] = fmaf(rad, xy, acc[q][1]);
                        acc[q][2] = fmaf(rad, xz, acc[q][2]);
                    } else if (m == 3) {
                        float dot = u0 * xx + u1 * xy + u2 * xz;
                        acc[q][0] = fmaf(rad, dot, acc[q][0]);
                    } else {
                        float cx = u1 * xz - u2 * xy;
                        float cy = u2 * xx - u0 * xz;
                        float cz = u0 * xy - u1 * xx;
                        acc[q][0] = fmaf(rad, cx, acc[q][0]);
                        acc[q][1] = fmaf(rad, cy, acc[q][1]);
                        acc[q][2] = fmaf(rad, cz, acc[q][2]);
                    }
                }
            }
        }
    }

    // ---- cross-thread reduction (32 contributors per output channel) ----
    __syncthreads();
    float* sPart = smem;   // weights dead; 256*24 = 6144 <= 7424 floats
    {
        const int base = tid * 24;
        #pragma unroll
        for (int q = 0; q < 8; q++) {
            sPart[base + q * 3 + 0] = acc[q][0];
            sPart[base + q * 3 + 1] = acc[q][1];
            sPart[base + q * 3 + 2] = acc[q][2];
        }
    }
    __syncthreads();

    const float nm = rsqrtf((float)(NN - 1));
    float* out1 = out + NN * 2 * CC;

    if (tid < CC * 3) {
        const int f    = tid / 3;
        const int comp = tid - f * 3;
        const int nh = f >> 5;
        const int cp = (f >> 3) & 3;
        const int q  = f & 7;
        float s = 0.0f;
        #pragma unroll
        for (int mm = 0; mm < 4; mm++) {
            #pragma unroll
            for (int rg = 0; rg < 8; rg++) {
                int tc = (mm * 2 + nh) * 32 + rg * 4 + cp;
                s += sPart[tc * 24 + q * 3 + comp];
            }
        }
        s *= nm;

        if (m == 0)      { if (comp == 0) out[a * 128 + f] = s; }
        else if (m == 1) { out1[a * 576 + f * 3 + comp] = s; }
        else if (m == 2) { out1[a * 576 + (64 + f) * 3 + comp] = s; }
        else if (m == 3) { if (comp == 0) out[a * 128 + 64 + f] = s; }
        else             { out1[a * 576 + (128 + f) * 3 + comp] = s; }
    }
}

extern "C" void kernel_launch(void* const* d_in, const int* in_sizes, int n_in,
                              void* d_out, int out_size) {
    const float* x0  = (const float*)d_in[0];
    const float* x1  = (const float*)d_in[1];
    const float* rbf = (const float*)d_in[2];
    const float* u   = (const float*)d_in[3];
    // d_in[4] = r_ij : unused (switching_fn == None)
    const float* w1  = (const float*)d_in[5];
    const float* b1  = (const float*)d_in[6];
    const float* w2  = (const float*)d_in[7];
    const float* b2  = (const float*)d_in[8];
    float* out = (float*)d_out;

    cudaFuncSetAttribute(conv_tfn_tc3_kernel,
                         cudaFuncAttributeMaxDynamicSharedMemorySize, SMEM_BYTES);

    dim3 grid(NN, 5);
    conv_tfn_tc3_kernel<<<grid, NT, SMEM_BYTES>>>(x0, x1, rbf, u, w1, b1, w2, b2, out);
}

// round 9
// speedup vs baseline: 3.5978x; 1.1942x over previous
#include <cuda_runtime.h>
#include <cstdint>

#define NN 512
#define CC 64
#define RR 32
#define BT 64
#define NT 128

#define PC1(k) (((k) & 3) * 8 + ((k) >> 2))     // k<32, stride 36
#define PC2(k) (((k) & 3) * 20 + ((k) >> 2))    // k<64, stride 80
// mma n-column for physical channel f (each thread owns 8 contiguous f)
#define PERMN(f) (((f) & 32) + ((((f) & 7) >> 1) << 3) + ((((f) >> 3) & 3) << 1) + ((f) & 1))

// smem layout (float units)
#define OFF_W1   0        // [64 n][36] tf32 (pc1)      | sPart overlay
#define OFF_W2   2304     // [64 n][80] tf32 (pc2)      |
#define OFF_RBF  7424     // [64 b][36] tf32 (pc1)
#define OFF_H    9728     // [64 b][80] tf32 (rotated pc2)
#define OFF_U    14848    // [192]
#define SMEM_FLOATS 15040
#define SMEM_BYTES (SMEM_FLOATS * 4)   // 60160 B -> 3 CTAs/SM

extern __shared__ float smem[];

__device__ __forceinline__ uint32_t f2tf(float x) {
    uint32_t u;
    asm("cvt.rna.tf32.f32 %0, %1;" : "=r"(u) : "f"(x));
    return u;
}

__device__ __forceinline__ void mma_tf32(float c[4], uint32_t a0, uint32_t a1,
                                         uint32_t a2, uint32_t a3,
                                         uint32_t b0, uint32_t b1) {
    asm volatile(
        "mma.sync.aligned.m16n8k8.row.col.f32.tf32.tf32.f32 "
        "{%0,%1,%2,%3}, {%4,%5,%6,%7}, {%8,%9}, {%0,%1,%2,%3};"
        : "+f"(c[0]), "+f"(c[1]), "+f"(c[2]), "+f"(c[3])
        : "r"(a0), "r"(a1), "r"(a2), "r"(a3), "r"(b0), "r"(b1));
}

__global__ __launch_bounds__(NT, 3)
void conv_tfn_tc4_kernel(const float* __restrict__ gx0,
                         const float* __restrict__ gx1,
                         const float* __restrict__ grbf,
                         const float* __restrict__ gu,
                         const float* __restrict__ gw1,
                         const float* __restrict__ gb1,
                         const float* __restrict__ gw2,
                         const float* __restrict__ gb2,
                         float* __restrict__ out)
{
    const int a    = blockIdx.x;
    const int m    = blockIdx.y;
    const int tid  = threadIdx.x;
    const int w    = tid >> 5;
    const int lane = tid & 31;
    const int mt    = w >> 1;        // 0..1 : rows [mt*32, mt*32+32)
    const int nhalf = w & 1;
    const int r0    = lane >> 2;
    const int cpos  = lane & 3;
    const int hrot  = (r0 >> 1) & 3; // H row-rotation for this thread's rows

    uint32_t* sW1u  = (uint32_t*)(smem + OFF_W1);
    uint32_t* sW2u  = (uint32_t*)(smem + OFF_W2);
    uint32_t* sRBFu = (uint32_t*)(smem + OFF_RBF);
    uint32_t* sHu   = (uint32_t*)(smem + OFF_H);
    float*    sU    = smem + OFF_U;

    // ---- stage weights (tf32, permuted-n cols, permuted-k rows) ----
    {
        const float* p = gw1 + (size_t)m * RR * CC;
        for (int i = tid; i < RR * CC; i += NT) {
            int k = i >> 6, f = i & 63;
            sW1u[PERMN(f) * 36 + PC1(k)] = f2tf(p[i]);
        }
        const float* q = gw2 + (size_t)m * CC * CC;
        for (int i = tid; i < CC * CC; i += NT) {
            int k = i >> 6, f = i & 63;
            sW2u[PERMN(f) * 80 + PC2(k)] = f2tf(q[i]);
        }
    }

    const int fbase = nhalf * 32 + cpos * 8;   // this thread's 8 contiguous channels

    float b1r[8], b2r[8];
    {
        float4 t0 = *(const float4*)(gb1 + m * CC + fbase);
        float4 t1 = *(const float4*)(gb1 + m * CC + fbase + 4);
        b1r[0]=t0.x; b1r[1]=t0.y; b1r[2]=t0.z; b1r[3]=t0.w;
        b1r[4]=t1.x; b1r[5]=t1.y; b1r[6]=t1.z; b1r[7]=t1.w;
        float4 s0 = *(const float4*)(gb2 + m * CC + fbase);
        float4 s1 = *(const float4*)(gb2 + m * CC + fbase + 4);
        b2r[0]=s0.x; b2r[1]=s0.y; b2r[2]=s0.z; b2r[3]=s0.w;
        b2r[4]=s1.x; b2r[5]=s1.y; b2r[6]=s1.z; b2r[7]=s1.w;
    }

    __syncthreads();   // weights visible

    // ---- hoist W1 B-fragments into registers (loop-invariant) ----
    uint32_t w1b[8][4];   // [nt*2+kt][4]
    #pragma unroll
    for (int nt = 0; nt < 4; nt++) {
        const int n = nhalf * 32 + nt * 8 + r0;
        #pragma unroll
        for (int kt = 0; kt < 2; kt++)
            *(uint4*)w1b[nt * 2 + kt] = *(const uint4*)&sW1u[n * 36 + cpos * 8 + kt * 4];
    }

    float acc[8][3];
    #pragma unroll
    for (int q = 0; q < 8; q++) { acc[q][0] = 0.f; acc[q][1] = 0.f; acc[q][2] = 0.f; }

    const int rbase = mt * 32 + r0;   // rows: rbase + msub*16 + {0,8}

    for (int bt = 0; bt < NN; bt += BT) {
        __syncthreads();

        // ---- stage rbf tile (tf32, pc1) ----
        {
            const float4* p = (const float4*)(grbf + (size_t)a * NN * RR + (size_t)bt * RR);
            #pragma unroll
            for (int t = 0; t < 4; t++) {
                int i = tid + t * NT;
                float4 v = p[i];
                int row = i >> 3, kq = i & 7;
                uint32_t* d = &sRBFu[row * 36 + kq];
                d[0]  = f2tf(v.x);
                d[8]  = f2tf(v.y);
                d[16] = f2tf(v.z);
                d[24] = f2tf(v.w);
            }
        }
        if (tid < BT * 3 / 4)
            ((float4*)sU)[tid] = ((const float4*)(gu + (size_t)a * NN * 3 + (size_t)bt * 3))[tid];
        __syncthreads();

        // ---- GEMM1: H = relu(rbf @ W1 + b1) ----
        float hc[2][4][4];
        #pragma unroll
        for (int s = 0; s < 2; s++)
            #pragma unroll
            for (int nt = 0; nt < 4; nt++)
                #pragma unroll
                for (int j = 0; j < 4; j++) hc[s][nt][j] = 0.f;

        #pragma unroll
        for (int kt = 0; kt < 2; kt++) {
            uint4 A0[2], A1[2];
            #pragma unroll
            for (int s = 0; s < 2; s++) {
                const int R = rbase + s * 16;
                A0[s] = *(const uint4*)&sRBFu[R * 36 + cpos * 8 + kt * 4];
                A1[s] = *(const uint4*)&sRBFu[(R + 8) * 36 + cpos * 8 + kt * 4];
            }
            #pragma unroll
            for (int nt = 0; nt < 4; nt++) {
                const uint32_t* B = w1b[nt * 2 + kt];
                #pragma unroll
                for (int s = 0; s < 2; s++) {
                    mma_tf32(hc[s][nt], A0[s].x, A1[s].x, A0[s].y, A1[s].y, B[0], B[1]);
                    mma_tf32(hc[s][nt], A0[s].z, A1[s].z, A0[s].w, A1[s].w, B[2], B[3]);
                }
            }
        }
        // epilogue: bias+relu+cvt -> sH (row-rotated slots)
        #pragma unroll
        for (int s = 0; s < 2; s++) {
            const int R = rbase + s * 16;
            #pragma unroll
            for (int nt = 0; nt < 4; nt++) {
                #pragma unroll
                for (int j = 0; j < 2; j++) {
                    const int c  = fbase + nt * 2 + j;
                    const int sl = ((((c & 3) + hrot) & 3) * 20) + (c >> 2);
                    sHu[R * 80 + sl]       = f2tf(fmaxf(hc[s][nt][j]     + b1r[nt*2+j], 0.f));
                    sHu[(R + 8) * 80 + sl] = f2tf(fmaxf(hc[s][nt][2 + j] + b1r[nt*2+j], 0.f));
                }
            }
        }
        // H rows [mt*32, +32) produced & consumed by this 2-warp pair only
        asm volatile("bar.sync %0, %1;" :: "r"(1 + mt), "r"(64) : "memory");

        // ---- GEMM2: rad = H @ W2 (B shared across both m-tiles) ----
        float rc[2][4][4];
        #pragma unroll
        for (int s = 0; s < 2; s++)
            #pragma unroll
            for (int nt = 0; nt < 4; nt++)
                #pragma unroll
                for (int j = 0; j < 4; j++) rc[s][nt][j] = 0.f;

        const int aoff = ((cpos + hrot) & 3) * 20;
        #pragma unroll
        for (int kt = 0; kt < 4; kt++) {
            uint4 A0[2], A1[2];
            #pragma unroll
            for (int s = 0; s < 2; s++) {
                const int R = rbase + s * 16;
                A0[s] = *(const uint4*)&sHu[R * 80 + aoff + kt * 4];
                A1[s] = *(const uint4*)&sHu[(R + 8) * 80 + aoff + kt * 4];
            }
            #pragma unroll
            for (int nt = 0; nt < 4; nt++) {
                const int n = nhalf * 32 + nt * 8 + r0;
                uint4 B = *(const uint4*)&sW2u[n * 80 + cpos * 20 + kt * 4];
                #pragma unroll
                for (int s = 0; s < 2; s++) {
                    mma_tf32(rc[s][nt], A0[s].x, A1[s].x, A0[s].y, A1[s].y, B.x, B.y);
                    mma_tf32(rc[s][nt], A0[s].z, A1[s].z, A0[s].w, A1[s].w, B.z, B.w);
                }
            }
        }

        // ---- fused CG contraction: x straight from global (L2-resident) ----
        #pragma unroll
        for (int s = 0; s < 2; s++) {
            #pragma unroll
            for (int rs = 0; rs < 2; rs++) {
                const int row  = rbase + s * 16 + rs * 8;
                const int grow = bt + row;
                if (grow == a) continue;   // diagonal mask
                if (m <= 1) {
                    float4 xa = *(const float4*)(gx0 + (size_t)grow * CC + fbase);
                    float4 xb = *(const float4*)(gx0 + (size_t)grow * CC + fbase + 4);
                    float xs[8] = {xa.x, xa.y, xa.z, xa.w, xb.x, xb.y, xb.z, xb.w};
                    if (m == 0) {
                        #pragma unroll
                        for (int q = 0; q < 8; q++) {
                            float rad = rc[s][q >> 1][rs * 2 + (q & 1)] + b2r[q];
                            acc[q][0] = fmaf(rad, xs[q], acc[q][0]);
                        }
                    } else {
                        float u0 = sU[row*3+0], u1 = sU[row*3+1], u2 = sU[row*3+2];
                        #pragma unroll
                        for (int q = 0; q < 8; q++) {
                            float rad = rc[s][q >> 1][rs * 2 + (q & 1)] + b2r[q];
                            float t = rad * xs[q];
                            acc[q][0] = fmaf(u0, t, acc[q][0]);
                            acc[q][1] = fmaf(u1, t, acc[q][1]);
                            acc[q][2] = fmaf(u2, t, acc[q][2]);
                        }
                    }
                } else {
                    float xr[24];
                    const float4* xp = (const float4*)(gx1 + (size_t)grow * CC * 3 + fbase * 3);
                    #pragma unroll
                    for (int t = 0; t < 6; t++)
                        *(float4*)&xr[t * 4] = xp[t];
                    float u0 = 0.f, u1 = 0.f, u2 = 0.f;
                    if (m >= 3) {
                        u0 = sU[row*3+0]; u1 = sU[row*3+1]; u2 = sU[row*3+2];
                    }
                    #pragma unroll
                    for (int q = 0; q < 8; q++) {
                        float rad = rc[s][q >> 1][rs * 2 + (q & 1)] + b2r[q];
                        float xx = xr[3*q], xy = xr[3*q+1], xz = xr[3*q+2];
                        if (m == 2) {
                            acc[q][0] = fmaf(rad, xx, acc[q][0]);
                            acc[q][1] = fmaf(rad, xy, acc[q][1]);
                            acc[q][2] = fmaf(rad, xz, acc[q][2]);
                        } else if (m == 3) {
                            float dot = u0 * xx + u1 * xy + u2 * xz;
                            acc[q][0] = fmaf(rad, dot, acc[q][0]);
                        } else {
                            float cx = u1 * xz - u2 * xy;
                            float cy = u2 * xx - u0 * xz;
                            float cz = u0 * xy - u1 * xx;
                            acc[q][0] = fmaf(rad, cx, acc[q][0]);
                            acc[q][1] = fmaf(rad, cy, acc[q][1]);
                            acc[q][2] = fmaf(rad, cz, acc[q][2]);
                        }
                    }
                }
            }
        }
    }

    // ---- cross-thread reduction (16 contributors per output channel) ----
    __syncthreads();
    float* sPart = smem;   // weights dead; 128*24 = 3072 floats
    {
        const int base = tid * 24;
        #pragma unroll
        for (int q = 0; q < 8; q++) {
            sPart[base + q * 3 + 0] = acc[q][0];
            sPart[base + q * 3 + 1] = acc[q][1];
            sPart[base + q * 3 + 2] = acc[q][2];
        }
    }
    __syncthreads();

    const float nm = rsqrtf((float)(NN - 1));
    float* out1 = out + NN * 2 * CC;

    for (int idx = tid; idx < CC * 3; idx += NT) {
        const int f    = idx / 3;
        const int comp = idx - f * 3;
        const int nh = f >> 5;
        const int cp = (f >> 3) & 3;
        const int q  = f & 7;
        float s = 0.0f;
        #pragma unroll
        for (int mm = 0; mm < 2; mm++) {
            #pragma unroll
            for (int rg = 0; rg < 8; rg++) {
                int tc = (mm * 2 + nh) * 32 + rg * 4 + cp;
                s += sPart[tc * 24 + q * 3 + comp];
            }
        }
        s *= nm;

        if (m == 0)      { if (comp == 0) out[a * 128 + f] = s; }
        else if (m == 1) { out1[a * 576 + f * 3 + comp] = s; }
        else if (m == 2) { out1[a * 576 + (64 + f) * 3 + comp] = s; }
        else if (m == 3) { if (comp == 0) out[a * 128 + 64 + f] = s; }
        else             { out1[a * 576 + (128 + f) * 3 + comp] = s; }
    }
}

extern "C" void kernel_launch(void* const* d_in, const int* in_sizes, int n_in,
                              void* d_out, int out_size) {
    const float* x0  = (const float*)d_in[0];
    const float* x1  = (const float*)d_in[1];
    const float* rbf = (const float*)d_in[2];
    const float* u   = (const float*)d_in[3];
    // d_in[4] = r_ij : unused (switching_fn == None)
    const float* w1  = (const float*)d_in[5];
    const float* b1  = (const float*)d_in[6];
    const float* w2  = (const float*)d_in[7];
    const float* b2  = (const float*)d_in[8];
    float* out = (float*)d_out;

    cudaFuncSetAttribute(conv_tfn_tc4_kernel,
                         cudaFuncAttributeMaxDynamicSharedMemorySize, SMEM_BYTES);

    dim3 grid(NN, 5);
    conv_tfn_tc4_kernel<<<grid, NT, SMEM_BYTES>>>(x0, x1, rbf, u, w1, b1, w2, b2, out);
}

// round 10
// speedup vs baseline: 3.6635x; 1.0182x over previous
#include <cuda_runtime.h>
#include <cstdint>

#define NN 512
#define CC 64
#define RR 32
#define BT 64
#define NT 128

#define PC2(k) (((k) & 3) * 20 + ((k) >> 2))    // k<64, stride 80
// mma n-column for physical channel f (each thread owns 8 contiguous f)
#define PERMN(f) (((f) & 32) + ((((f) & 7) >> 1) << 3) + ((((f) >> 3) & 3) << 1) + ((f) & 1))

// smem layout (float units)
#define OFF_W1   0        // [64 n][36] tf32 (pc1)   | sPart overlay
#define OFF_W2   2304     // [64 n][80] tf32 (pc2)   |
#define OFF_H    7424     // [64 b][80] tf32 (rotated pc2)
#define SMEM_FLOATS 12544
#define SMEM_BYTES (SMEM_FLOATS * 4)   // 50176 B

// rbf pre-converted to tf32 bits, permuted-k layout: [a][b][pc1(k)]
__device__ uint32_t g_rbf_tf[NN * NN * RR];

extern __shared__ float smem[];

__device__ __forceinline__ uint32_t f2tf(float x) {
    uint32_t u;
    asm("cvt.rna.tf32.f32 %0, %1;" : "=r"(u) : "f"(x));
    return u;
}

__device__ __forceinline__ void mma_tf32(float c[4], uint32_t a0, uint32_t a1,
                                         uint32_t a2, uint32_t a3,
                                         uint32_t b0, uint32_t b1) {
    asm volatile(
        "mma.sync.aligned.m16n8k8.row.col.f32.tf32.tf32.f32 "
        "{%0,%1,%2,%3}, {%4,%5,%6,%7}, {%8,%9}, {%0,%1,%2,%3};"
        : "+f"(c[0]), "+f"(c[1]), "+f"(c[2]), "+f"(c[3])
        : "r"(a0), "r"(a1), "r"(a2), "r"(a3), "r"(b0), "r"(b1));
}

// ---- prep: rbf fp32 -> tf32 bits in permuted-k fragment layout ----
__global__ void prep_rbf_kernel(const float* __restrict__ grbf) {
    int i = blockIdx.x * blockDim.x + threadIdx.x;   // over NN*NN*8 float4s
    float4 v = ((const float4*)grbf)[i];
    int pair = i >> 3;       // (a,b) row
    int kq   = i & 7;        // k/4
    uint32_t* d = g_rbf_tf + (size_t)pair * RR + kq;
    d[0]  = f2tf(v.x);       // k = 4*kq+0 -> slot kq
    d[8]  = f2tf(v.y);       // k = 4*kq+1 -> slot 8+kq
    d[16] = f2tf(v.z);
    d[24] = f2tf(v.w);
}

__global__ __launch_bounds__(NT, 3)
void conv_tfn_tc5_kernel(const float* __restrict__ gx0,
                         const float* __restrict__ gx1,
                         const float* __restrict__ gu,
                         const float* __restrict__ gw1,
                         const float* __restrict__ gb1,
                         const float* __restrict__ gw2,
                         const float* __restrict__ gb2,
                         float* __restrict__ out)
{
    const int a    = blockIdx.x;
    const int m    = blockIdx.y;
    const int tid  = threadIdx.x;
    const int w    = tid >> 5;
    const int lane = tid & 31;
    const int mt    = w >> 1;        // 0..1 : rows [mt*32, mt*32+32)
    const int nhalf = w & 1;
    const int r0    = lane >> 2;
    const int cpos  = lane & 3;
    const int hrot  = (r0 >> 1) & 3;

    uint32_t* sW1u = (uint32_t*)(smem + OFF_W1);
    uint32_t* sW2u = (uint32_t*)(smem + OFF_W2);
    uint32_t* sHu  = (uint32_t*)(smem + OFF_H);

    // ---- stage weights (tf32, permuted-n cols, permuted-k rows) ----
    {
        const float* p = gw1 + (size_t)m * RR * CC;
        for (int i = tid; i < RR * CC; i += NT) {
            int k = i >> 6, f = i & 63;
            sW1u[PERMN(f) * 36 + ((k & 3) * 8 + (k >> 2))] = f2tf(p[i]);
        }
        const float* q = gw2 + (size_t)m * CC * CC;
        for (int i = tid; i < CC * CC; i += NT) {
            int k = i >> 6, f = i & 63;
            sW2u[PERMN(f) * 80 + PC2(k)] = f2tf(q[i]);
        }
    }

    const int fbase = nhalf * 32 + cpos * 8;

    float b1r[8], b2r[8];
    {
        float4 t0 = *(const float4*)(gb1 + m * CC + fbase);
        float4 t1 = *(const float4*)(gb1 + m * CC + fbase + 4);
        b1r[0]=t0.x; b1r[1]=t0.y; b1r[2]=t0.z; b1r[3]=t0.w;
        b1r[4]=t1.x; b1r[5]=t1.y; b1r[6]=t1.z; b1r[7]=t1.w;
        float4 s0 = *(const float4*)(gb2 + m * CC + fbase);
        float4 s1 = *(const float4*)(gb2 + m * CC + fbase + 4);
        b2r[0]=s0.x; b2r[1]=s0.y; b2r[2]=s0.z; b2r[3]=s0.w;
        b2r[4]=s1.x; b2r[5]=s1.y; b2r[6]=s1.z; b2r[7]=s1.w;
    }

    __syncthreads();   // weights visible

    // ---- hoist W1 B-fragments to registers (loop-invariant) ----
    uint32_t w1b[8][4];
    #pragma unroll
    for (int nt = 0; nt < 4; nt++) {
        const int n = nhalf * 32 + nt * 8 + r0;
        #pragma unroll
        for (int kt = 0; kt < 2; kt++)
            *(uint4*)w1b[nt * 2 + kt] = *(const uint4*)&sW1u[n * 36 + cpos * 8 + kt * 4];
    }

    float acc[8][3];
    #pragma unroll
    for (int q = 0; q < 8; q++) { acc[q][0] = 0.f; acc[q][1] = 0.f; acc[q][2] = 0.f; }

    const int rbase = mt * 32 + r0;
    const uint32_t* rbA = g_rbf_tf + (size_t)a * NN * RR;
    const float*    uA  = gu + (size_t)a * NN * 3;

    for (int bt = 0; bt < NN; bt += BT) {
        // ---- GEMM1: H = relu(rbf @ W1 + b1); A straight from global (L2) ----
        float hc[2][4][4];
        #pragma unroll
        for (int s = 0; s < 2; s++)
            #pragma unroll
            for (int nt = 0; nt < 4; nt++)
                #pragma unroll
                for (int j = 0; j < 4; j++) hc[s][nt][j] = 0.f;

        #pragma unroll
        for (int kt = 0; kt < 2; kt++) {
            uint4 A0[2], A1[2];
            #pragma unroll
            for (int s = 0; s < 2; s++) {
                const int R = bt + rbase + s * 16;
                A0[s] = *(const uint4*)&rbA[(size_t)R * RR + cpos * 8 + kt * 4];
                A1[s] = *(const uint4*)&rbA[(size_t)(R + 8) * RR + cpos * 8 + kt * 4];
            }
            #pragma unroll
            for (int nt = 0; nt < 4; nt++) {
                const uint32_t* B = w1b[nt * 2 + kt];
                #pragma unroll
                for (int s = 0; s < 2; s++) {
                    mma_tf32(hc[s][nt], A0[s].x, A1[s].x, A0[s].y, A1[s].y, B[0], B[1]);
                    mma_tf32(hc[s][nt], A0[s].z, A1[s].z, A0[s].w, A1[s].w, B[2], B[3]);
                }
            }
        }

        // pair barrier: our pair's GEMM2 reads of the previous tile's H are done
        asm volatile("bar.sync %0, %1;" :: "r"(1 + mt), "r"(64) : "memory");

        // epilogue: bias+relu+cvt -> sH (row-rotated slots)
        #pragma unroll
        for (int s = 0; s < 2; s++) {
            const int R = rbase + s * 16;
            #pragma unroll
            for (int nt = 0; nt < 4; nt++) {
                #pragma unroll
                for (int j = 0; j < 2; j++) {
                    const int c  = fbase + nt * 2 + j;
                    const int sl = ((((c & 3) + hrot) & 3) * 20) + (c >> 2);
                    sHu[R * 80 + sl]       = f2tf(fmaxf(hc[s][nt][j]     + b1r[nt*2+j], 0.f));
                    sHu[(R + 8) * 80 + sl] = f2tf(fmaxf(hc[s][nt][2 + j] + b1r[nt*2+j], 0.f));
                }
            }
        }
        // pair barrier: H writes visible to partner warp
        asm volatile("bar.sync %0, %1;" :: "r"(1 + mt), "r"(64) : "memory");

        // ---- GEMM2: rad = H @ W2 ----
        float rc[2][4][4];
        #pragma unroll
        for (int s = 0; s < 2; s++)
            #pragma unroll
            for (int nt = 0; nt < 4; nt++)
                #pragma unroll
                for (int j = 0; j < 4; j++) rc[s][nt][j] = 0.f;

        const int aoff = ((cpos + hrot) & 3) * 20;
        #pragma unroll
        for (int kt = 0; kt < 4; kt++) {
            uint4 A0[2], A1[2];
            #pragma unroll
            for (int s = 0; s < 2; s++) {
                const int R = rbase + s * 16;
                A0[s] = *(const uint4*)&sHu[R * 80 + aoff + kt * 4];
                A1[s] = *(const uint4*)&sHu[(R + 8) * 80 + aoff + kt * 4];
            }
            #pragma unroll
            for (int nt = 0; nt < 4; nt++) {
                const int n = nhalf * 32 + nt * 8 + r0;
                uint4 B = *(const uint4*)&sW2u[n * 80 + cpos * 20 + kt * 4];
                #pragma unroll
                for (int s = 0; s < 2; s++) {
                    mma_tf32(rc[s][nt], A0[s].x, A1[s].x, A0[s].y, A1[s].y, B.x, B.y);
                    mma_tf32(rc[s][nt], A0[s].z, A1[s].z, A0[s].w, A1[s].w, B.z, B.w);
                }
            }
        }

        // ---- fused CG contraction: x and u straight from global ----
        #pragma unroll
        for (int s = 0; s < 2; s++) {
            #pragma unroll
            for (int rs = 0; rs < 2; rs++) {
                const int row  = rbase + s * 16 + rs * 8;
                const int grow = bt + row;
                if (grow == a) continue;   // diagonal mask
                if (m <= 1) {
                    float4 xa = *(const float4*)(gx0 + (size_t)grow * CC + fbase);
                    float4 xb = *(const float4*)(gx0 + (size_t)grow * CC + fbase + 4);
                    float xs[8] = {xa.x, xa.y, xa.z, xa.w, xb.x, xb.y, xb.z, xb.w};
                    if (m == 0) {
                        #pragma unroll
                        for (int q = 0; q < 8; q++) {
                            float rad = rc[s][q >> 1][rs * 2 + (q & 1)] + b2r[q];
                            acc[q][0] = fmaf(rad, xs[q], acc[q][0]);
                        }
                    } else {
                        float u0 = uA[grow*3+0], u1 = uA[grow*3+1], u2 = uA[grow*3+2];
                        #pragma unroll
                        for (int q = 0; q < 8; q++) {
                            float rad = rc[s][q >> 1][rs * 2 + (q & 1)] + b2r[q];
                            float t = rad * xs[q];
                            acc[q][0] = fmaf(u0, t, acc[q][0]);
                            acc[q][1] = fmaf(u1, t, acc[q][1]);
                            acc[q][2] = fmaf(u2, t, acc[q][2]);
                        }
                    }
                } else {
                    float xr[24];
                    const float4* xp = (const float4*)(gx1 + (size_t)grow * CC * 3 + fbase * 3);
                    #pragma unroll
                    for (int t = 0; t < 6; t++)
                        *(float4*)&xr[t * 4] = xp[t];
                    float u0 = 0.f, u1 = 0.f, u2 = 0.f;
                    if (m >= 3) {
                        u0 = uA[grow*3+0]; u1 = uA[grow*3+1]; u2 = uA[grow*3+2];
                    }
                    #pragma unroll
                    for (int q = 0; q < 8; q++) {
                        float rad = rc[s][q >> 1][rs * 2 + (q & 1)] + b2r[q];
                        float xx = xr[3*q], xy = xr[3*q+1], xz = xr[3*q+2];
                        if (m == 2) {
                            acc[q][0] = fmaf(rad, xx, acc[q][0]);
                            acc[q][1] = fmaf(rad, xy, acc[q][1]);
                            acc[q][2] = fmaf(rad, xz, acc[q][2]);
                        } else if (m == 3) {
                            float dot = u0 * xx + u1 * xy + u2 * xz;
                            acc[q][0] = fmaf(rad, dot, acc[q][0]);
                        } else {
                            float cx = u1 * xz - u2 * xy;
                            float cy = u2 * xx - u0 * xz;
                            float cz = u0 * xy - u1 * xx;
                            acc[q][0] = fmaf(rad, cx, acc[q][0]);
                            acc[q][1] = fmaf(rad, cy, acc[q][1]);
                            acc[q][2] = fmaf(rad, cz, acc[q][2]);
                        }
                    }
                }
            }
        }
    }

    // ---- cross-thread reduction (16 contributors per output channel) ----
    __syncthreads();
    float* sPart = smem;   // weights dead; 128*24 = 3072 floats
    {
        const int base = tid * 24;
        #pragma unroll
        for (int q = 0; q < 8; q++) {
            sPart[base + q * 3 + 0] = acc[q][0];
            sPart[base + q * 3 + 1] = acc[q][1];
            sPart[base + q * 3 + 2] = acc[q][2];
        }
    }
    __syncthreads();

    const float nm = rsqrtf((float)(NN - 1));
    float* out1 = out + NN * 2 * CC;

    for (int idx = tid; idx < CC * 3; idx += NT) {
        const int f    = idx / 3;
        const int comp = idx - f * 3;
        const int nh = f >> 5;
        const int cp = (f >> 3) & 3;
        const int q  = f & 7;
        float s = 0.0f;
        #pragma unroll
        for (int mm = 0; mm < 2; mm++) {
            #pragma unroll
            for (int rg = 0; rg < 8; rg++) {
                int tc = (mm * 2 + nh) * 32 + rg * 4 + cp;
                s += sPart[tc * 24 + q * 3 + comp];
            }
        }
        s *= nm;

        if (m == 0)      { if (comp == 0) out[a * 128 + f] = s; }
        else if (m == 1) { out1[a * 576 + f * 3 + comp] = s; }
        else if (m == 2) { out1[a * 576 + (64 + f) * 3 + comp] = s; }
        else if (m == 3) { if (comp == 0) out[a * 128 + 64 + f] = s; }
        else             { out1[a * 576 + (128 + f) * 3 + comp] = s; }
    }
}

extern "C" void kernel_launch(void* const* d_in, const int* in_sizes, int n_in,
                              void* d_out, int out_size) {
    const float* x0  = (const float*)d_in[0];
    const float* x1  = (const float*)d_in[1];
    const float* rbf = (const float*)d_in[2];
    const float* u   = (const float*)d_in[3];
    // d_in[4] = r_ij : unused (switching_fn == None)
    const float* w1  = (const float*)d_in[5];
    const float* b1  = (const float*)d_in[6];
    const float* w2  = (const float*)d_in[7];
    const float* b2  = (const float*)d_in[8];
    float* out = (float*)d_out;

    // 1) convert rbf to tf32-permuted fragment layout
    prep_rbf_kernel<<<NN * NN * 8 / 256, 256>>>(rbf);

    // 2) main fused kernel
    cudaFuncSetAttribute(conv_tfn_tc5_kernel,
                         cudaFuncAttributeMaxDynamicSharedMemorySize, SMEM_BYTES);
    dim3 grid(NN, 5);
    conv_tfn_tc5_kernel<<<grid, NT, SMEM_BYTES>>>(x0, x1, u, w1, b1, w2, b2, out);
}